// round 5
// baseline (speedup 1.0000x reference)
#include <cuda_runtime.h>
#include <cstdint>
#include <math.h>

#define TOK   8192
#define EMB_  768
#define FF_   3072
#define HEADS_ 12
#define SEQ_  2048
#define LDQKV 2304

// ---------------- scratch (device globals; no allocation allowed) ----------
__device__ float g_ln  [TOK * EMB_];
__device__ float g_qkv [TOK * LDQKV];
__device__ float g_ctx [TOK * EMB_];
__device__ float g_x2  [TOK * EMB_];
__device__ float g_ffh [(size_t)TOK * FF_];
__device__ float g_wqkv[EMB_ * LDQKV];
__device__ float g_wo  [EMB_ * EMB_];
__device__ float g_w1  [EMB_ * FF_];
__device__ float g_w2  [FF_ * EMB_];

// ---------------- helpers ---------------------------------------------------
__device__ __forceinline__ uint32_t s2u(const void* p) {
    uint32_t a;
    asm("{ .reg .u64 t; cvta.to.shared.u64 t, %1; cvt.u32.u64 %0, t; }" : "=r"(a) : "l"(p));
    return a;
}
__device__ __forceinline__ float tf32r(float x) {
    uint32_t u; asm("cvt.rna.tf32.f32 %0, %1;" : "=r"(u) : "f"(x));
    return __uint_as_float(u);
}
__device__ __forceinline__ float gelu_f(float x) {
    const float c = 0.79788456080286535588f;
    float t = tanhf(c * (x + 0.044715f * x * x * x));
    return 0.5f * x * (1.f + t);
}
__device__ __forceinline__ void mma8(float c[4], const uint32_t a[4],
                                     uint32_t b0, uint32_t b1) {
    asm volatile("mma.sync.aligned.m16n8k8.row.col.f32.tf32.tf32.f32 "
        "{%0,%1,%2,%3}, {%4,%5,%6,%7}, {%8,%9}, {%0,%1,%2,%3};"
        : "+f"(c[0]), "+f"(c[1]), "+f"(c[2]), "+f"(c[3])
        : "r"(a[0]), "r"(a[1]), "r"(a[2]), "r"(a[3]), "r"(b0), "r"(b1));
}

#define CPA16(d, s) \
    asm volatile("cp.async.cg.shared.global [%0], [%1], 16;" :: "r"(d), "l"(s))
#define CPA_COMMIT() asm volatile("cp.async.commit_group;" ::: "memory")
#define CPA_WAIT2()  asm volatile("cp.async.wait_group 2;" ::: "memory")

// ---------------- weight prep -----------------------------------------------
__global__ __launch_bounds__(256) void round_copy(const float* __restrict__ s,
                                                  float* __restrict__ d, int n)
{
    int i = (blockIdx.x * 256 + threadIdx.x) * 4;
    if (i < n) {
        float4 v = *(const float4*)(s + i);
        v.x = tf32r(v.x); v.y = tf32r(v.y); v.z = tf32r(v.z); v.w = tf32r(v.w);
        *(float4*)(d + i) = v;
    }
}
__global__ __launch_bounds__(256) void pack_qkv(const float* __restrict__ wq,
                                                const float* __restrict__ wk,
                                                const float* __restrict__ wv,
                                                float* __restrict__ d)
{
    int i = blockIdx.x * 256 + threadIdx.x;
    int k = i / EMB_, n = i % EMB_;
    d[(size_t)k * LDQKV + n        ] = tf32r(wq[i]);
    d[(size_t)k * LDQKV + n + 768  ] = tf32r(wk[i]);
    d[(size_t)k * LDQKV + n + 1536 ] = tf32r(wv[i]);
}

// ---------------- layernorm --------------------------------------------------
__global__ __launch_bounds__(256) void ln_k(const float* __restrict__ x,
                                            const float* __restrict__ sc,
                                            const float* __restrict__ sh,
                                            float* __restrict__ out)
{
    int row = blockIdx.x;
    const float* xr = x + (size_t)row * EMB_;
    int t = threadIdx.x;
    float v0 = xr[t], v1 = xr[t + 256], v2 = xr[t + 512];

    __shared__ float red[8];
    float s = v0 + v1 + v2;
    #pragma unroll
    for (int o = 16; o; o >>= 1) s += __shfl_xor_sync(0xffffffffu, s, o);
    if ((t & 31) == 0) red[t >> 5] = s;
    __syncthreads();
    float mean = 0.f;
    #pragma unroll
    for (int i = 0; i < 8; i++) mean += red[i];
    mean *= (1.f / 768.f);

    float d0 = v0 - mean, d1 = v1 - mean, d2 = v2 - mean;
    float vs = d0 * d0 + d1 * d1 + d2 * d2;
    #pragma unroll
    for (int o = 16; o; o >>= 1) vs += __shfl_xor_sync(0xffffffffu, vs, o);
    __syncthreads();
    if ((t & 31) == 0) red[t >> 5] = vs;
    __syncthreads();
    float var = 0.f;
    #pragma unroll
    for (int i = 0; i < 8; i++) var += red[i];
    var *= (1.f / 768.f);
    float rstd = rsqrtf(var + 1e-5f);

    float* orow = out + (size_t)row * EMB_;
    orow[t      ] = tf32r(d0 * rstd * sc[t      ] + sh[t      ]);
    orow[t + 256] = tf32r(d1 * rstd * sc[t + 256] + sh[t + 256]);
    orow[t + 512] = tf32r(d2 * rstd * sc[t + 512] + sh[t + 512]);
}

// ---------------- tf32 mma.sync GEMM: C[M,N] = A[M,K] @ B[K,N] -------------
// CTA 256x128 tile, 256 threads = 8 warps (4m x 2n), warp tile 64x64.
// 3-stage cp.async pipeline, K=32/stage. Conflict-free pitches.
#define APITCH 36
#define BPITCH 136
#define A_FLOATS (256 * APITCH)                 // 9216
#define STAGE_FLOATS (A_FLOATS + 32 * BPITCH)   // 13568
#define NSTG 3
#define GEMM_SMEM (NSTG * STAGE_FLOATS * 4)     // 162816 B

template<int EPI>   // 0 plain; 1 +bias+res; 2 +bias, gelu, tf32-round
__global__ __launch_bounds__(256, 1) void mmagemm(const float* __restrict__ A,
                                                  const float* __restrict__ B,
                                                  const float* __restrict__ bias,
                                                  const float* __restrict__ res,
                                                  float* __restrict__ C,
                                                  int Kd, int N, int ldc, int KT)
{
    extern __shared__ __align__(16) float smf[];
    int tid = threadIdx.x, lane = tid & 31, w = tid >> 5;
    int wm = w >> 1, wn = w & 1;      // 4 x 2
    int bm = blockIdx.y, bn = blockIdx.x;
    int gr = lane >> 2, t4 = lane & 3;

    float acc[4][8][4];
    #pragma unroll
    for (int i = 0; i < 4; i++)
        #pragma unroll
        for (int j = 0; j < 8; j++)
            #pragma unroll
            for (int e = 0; e < 4; e++) acc[i][j][e] = 0.f;

    auto issue = [&](int kt) {
        float* st = smf + (kt % NSTG) * STAGE_FLOATS;
        int k0 = kt * 32;
        #pragma unroll
        for (int i = 0; i < 8; i++) {                 // A: 256 rows x 32
            int chunk = tid + i * 256;                // 0..2047
            int row = chunk >> 3, kq = chunk & 7;
            CPA16(s2u(st + row * APITCH + kq * 4),
                  A + (size_t)(bm * 256 + row) * Kd + k0 + kq * 4);
        }
        #pragma unroll
        for (int i = 0; i < 4; i++) {                 // B: 32 x 128
            int chunk = tid + i * 256;
            int kr = chunk >> 5, nq = chunk & 31;
            CPA16(s2u(st + A_FLOATS + kr * BPITCH + nq * 4),
                  B + (size_t)(k0 + kr) * N + bn * 128 + nq * 4);
        }
    };

    issue(0); CPA_COMMIT();
    issue(1); CPA_COMMIT();

    for (int kt = 0; kt < KT; kt++) {
        if (kt + 2 < KT) issue(kt + 2);
        CPA_COMMIT();
        CPA_WAIT2();
        __syncthreads();

        const float* st = smf + (kt % NSTG) * STAGE_FLOATS;
        const uint32_t* As = (const uint32_t*)st;
        const uint32_t* Bs = (const uint32_t*)(st + A_FLOATS);

        #pragma unroll
        for (int kc = 0; kc < 4; kc++) {
            int kb = kc * 8;
            uint32_t a[4][4];
            #pragma unroll
            for (int mt = 0; mt < 4; mt++) {
                int r = wm * 64 + mt * 16 + gr;
                a[mt][0] = As[(r    ) * APITCH + kb + t4    ];
                a[mt][1] = As[(r + 8) * APITCH + kb + t4    ];
                a[mt][2] = As[(r    ) * APITCH + kb + t4 + 4];
                a[mt][3] = As[(r + 8) * APITCH + kb + t4 + 4];
            }
            uint32_t b[8][2];
            #pragma unroll
            for (int nt = 0; nt < 8; nt++) {
                int n = wn * 64 + nt * 8 + gr;
                b[nt][0] = Bs[(kb + t4    ) * BPITCH + n];
                b[nt][1] = Bs[(kb + t4 + 4) * BPITCH + n];
            }
            #pragma unroll
            for (int mt = 0; mt < 4; mt++)
                #pragma unroll
                for (int nt = 0; nt < 8; nt++)
                    mma8(acc[mt][nt], a[mt], b[nt][0], b[nt][1]);
        }
        __syncthreads();
    }

    float bv[8][2];
    if (EPI >= 1) {
        #pragma unroll
        for (int nt = 0; nt < 8; nt++) {
            int col = bn * 128 + wn * 64 + nt * 8 + t4 * 2;
            bv[nt][0] = bias[col]; bv[nt][1] = bias[col + 1];
        }
    }
    #pragma unroll
    for (int mt = 0; mt < 4; mt++) {
        #pragma unroll
        for (int rr = 0; rr < 2; rr++) {
            int row = bm * 256 + wm * 64 + mt * 16 + gr + rr * 8;
            size_t off = (size_t)row * ldc + bn * 128 + wn * 64 + t4 * 2;
            #pragma unroll
            for (int nt = 0; nt < 8; nt++) {
                float v0 = acc[mt][nt][rr * 2 + 0];
                float v1 = acc[mt][nt][rr * 2 + 1];
                if (EPI >= 1) { v0 += bv[nt][0]; v1 += bv[nt][1]; }
                if (EPI == 2) { v0 = tf32r(gelu_f(v0)); v1 = tf32r(gelu_f(v1)); }
                if (EPI == 1) {
                    float2 r2 = *(const float2*)&res[off + nt * 8];
                    v0 += r2.x; v1 += r2.y;
                }
                *(float2*)&C[off + nt * 8] = make_float2(v0, v1);
            }
        }
    }
}

// ---------------- causal flash attention, tf32 mma.sync --------------------
#define AP 68
#define ATTN_SMEM ((64 + 64 + 128) * AP * 4)   // 69632 B

__global__ __launch_bounds__(256) void attn_mma(const float* __restrict__ Q,
                                                const float* __restrict__ K,
                                                const float* __restrict__ V,
                                                float* __restrict__ O)
{
    extern __shared__ __align__(16) float sm[];
    float* Ks = sm;
    float* Vt = sm + 64 * AP;
    float* Ps = sm + 128 * AP;
    const uint32_t* Ku = (const uint32_t*)Ks;
    const uint32_t* Vu = (const uint32_t*)Vt;
    const uint32_t* Pu = (const uint32_t*)Ps;

    int tid = threadIdx.x, lane = tid & 31, w = tid >> 5;
    int gr = lane >> 2, t4 = lane & 3;
    int bh = blockIdx.y, bb = bh / HEADS_, h = bh % HEADS_;
    int q0 = blockIdx.x * 128;
    size_t baseq = (size_t)bb * SEQ_ * LDQKV + (size_t)h * 64;
    size_t baseo = (size_t)bb * SEQ_ * EMB_  + (size_t)h * 64;
    int r = w * 16 + gr;

    for (int i = tid; i < 128 * 64; i += 256) {
        int rr = i >> 6, dd = i & 63;
        Ps[rr * AP + dd] = tf32r(Q[baseq + (size_t)(q0 + rr) * LDQKV + dd] * 0.125f);
    }
    __syncthreads();
    uint32_t qf[8][4];
    #pragma unroll
    for (int kc = 0; kc < 8; kc++) {
        int kb = kc * 8;
        qf[kc][0] = Pu[(r    ) * AP + kb + t4    ];
        qf[kc][1] = Pu[(r + 8) * AP + kb + t4    ];
        qf[kc][2] = Pu[(r    ) * AP + kb + t4 + 4];
        qf[kc][3] = Pu[(r + 8) * AP + kb + t4 + 4];
    }

    float m0 = -1e30f, m1 = -1e30f, l0 = 0.f, l1 = 0.f;
    float o[8][4];
    #pragma unroll
    for (int nt = 0; nt < 8; nt++)
        #pragma unroll
        for (int e = 0; e < 4; e++) o[nt][e] = 0.f;

    int jmaxt = 2 * blockIdx.x + 1;
    int qlo = q0 + r;

    for (int j = 0; j <= jmaxt; j++) {
        __syncthreads();
        for (int i = tid; i < 64 * 64; i += 256) {
            int rr = i >> 6, dd = i & 63;
            size_t g = baseq + (size_t)(j * 64 + rr) * LDQKV + dd;
            Ks[rr * AP + dd] = tf32r(K[g]);
            Vt[dd * AP + rr] = tf32r(V[g]);
        }
        __syncthreads();

        float s[8][4];
        #pragma unroll
        for (int nt = 0; nt < 8; nt++)
            #pragma unroll
            for (int e = 0; e < 4; e++) s[nt][e] = 0.f;
        #pragma unroll
        for (int kc = 0; kc < 8; kc++) {
            int kb = kc * 8;
            #pragma unroll
            for (int nt = 0; nt < 8; nt++) {
                uint32_t b0 = Ku[(nt * 8 + gr) * AP + kb + t4    ];
                uint32_t b1 = Ku[(nt * 8 + gr) * AP + kb + t4 + 4];
                mma8(s[nt], qf[kc], b0, b1);
            }
        }

        if (j * 64 + 63 > q0 + w * 16) {
            #pragma unroll
            for (int nt = 0; nt < 8; nt++) {
                int c0 = j * 64 + nt * 8 + 2 * t4;
                if (c0     > qlo    ) s[nt][0] = -1e30f;
                if (c0 + 1 > qlo    ) s[nt][1] = -1e30f;
                if (c0     > qlo + 8) s[nt][2] = -1e30f;
                if (c0 + 1 > qlo + 8) s[nt][3] = -1e30f;
            }
        }

        float mt0 = -1e30f, mt1 = -1e30f;
        #pragma unroll
        for (int nt = 0; nt < 8; nt++) {
            mt0 = fmaxf(mt0, fmaxf(s[nt][0], s[nt][1]));
            mt1 = fmaxf(mt1, fmaxf(s[nt][2], s[nt][3]));
        }
        mt0 = fmaxf(mt0, __shfl_xor_sync(0xffffffffu, mt0, 1));
        mt0 = fmaxf(mt0, __shfl_xor_sync(0xffffffffu, mt0, 2));
        mt1 = fmaxf(mt1, __shfl_xor_sync(0xffffffffu, mt1, 1));
        mt1 = fmaxf(mt1, __shfl_xor_sync(0xffffffffu, mt1, 2));
        float mn0 = fmaxf(m0, mt0), mn1 = fmaxf(m1, mt1);
        float a0 = __expf(m0 - mn0), a1 = __expf(m1 - mn1);
        float ps0 = 0.f, ps1 = 0.f;
        #pragma unroll
        for (int nt = 0; nt < 8; nt++) {
            s[nt][0] = __expf(s[nt][0] - mn0); ps0 += s[nt][0];
            s[nt][1] = __expf(s[nt][1] - mn0); ps0 += s[nt][1];
            s[nt][2] = __expf(s[nt][2] - mn1); ps1 += s[nt][2];
            s[nt][3] = __expf(s[nt][3] - mn1); ps1 += s[nt][3];
        }
        ps0 += __shfl_xor_sync(0xffffffffu, ps0, 1);
        ps0 += __shfl_xor_sync(0xffffffffu, ps0, 2);
        ps1 += __shfl_xor_sync(0xffffffffu, ps1, 1);
        ps1 += __shfl_xor_sync(0xffffffffu, ps1, 2);
        l0 = l0 * a0 + ps0; l1 = l1 * a1 + ps1;
        m0 = mn0; m1 = mn1;
        #pragma unroll
        for (int nt = 0; nt < 8; nt++) {
            o[nt][0] *= a0; o[nt][1] *= a0; o[nt][2] *= a1; o[nt][3] *= a1;
        }

        #pragma unroll
        for (int nt = 0; nt < 8; nt++) {
            int cc = nt * 8 + 2 * t4;
            *(float2*)&Ps[(r    ) * AP + cc] = make_float2(tf32r(s[nt][0]), tf32r(s[nt][1]));
            *(float2*)&Ps[(r + 8) * AP + cc] = make_float2(tf32r(s[nt][2]), tf32r(s[nt][3]));
        }
        __syncwarp();

        #pragma unroll
        for (int kc = 0; kc < 8; kc++) {
            int kb = kc * 8;
            uint32_t pa[4];
            pa[0] = Pu[(r    ) * AP + kb + t4    ];
            pa[1] = Pu[(r + 8) * AP + kb + t4    ];
            pa[2] = Pu[(r    ) * AP + kb + t4 + 4];
            pa[3] = Pu[(r + 8) * AP + kb + t4 + 4];
            #pragma unroll
            for (int nt = 0; nt < 8; nt++) {
                uint32_t b0 = Vu[(nt * 8 + gr) * AP + kb + t4    ];
                uint32_t b1 = Vu[(nt * 8 + gr) * AP + kb + t4 + 4];
                mma8(o[nt], pa, b0, b1);
            }
        }
    }

    float inv0 = 1.f / l0, inv1 = 1.f / l1;
    size_t off0 = baseo + (size_t)(q0 + r    ) * EMB_;
    size_t off1 = baseo + (size_t)(q0 + r + 8) * EMB_;
    #pragma unroll
    for (int nt = 0; nt < 8; nt++) {
        int cc = nt * 8 + 2 * t4;
        *(float2*)&O[off0 + cc] = make_float2(tf32r(o[nt][0] * inv0), tf32r(o[nt][1] * inv0));
        *(float2*)&O[off1 + cc] = make_float2(tf32r(o[nt][2] * inv1), tf32r(o[nt][3] * inv1));
    }
}

// ---------------- launch ---------------------------------------------------
extern "C" void kernel_launch(void* const* d_in, const int* in_sizes, int n_in,
                              void* d_out, int out_size)
{
    const float* x    = (const float*)d_in[0];
    const float* ln1s = (const float*)d_in[1];
    const float* ln1b = (const float*)d_in[2];
    const float* wq   = (const float*)d_in[3];
    const float* wk   = (const float*)d_in[4];
    const float* wv   = (const float*)d_in[5];
    const float* wo   = (const float*)d_in[6];
    const float* bo   = (const float*)d_in[7];
    const float* ln2s = (const float*)d_in[8];
    const float* ln2b = (const float*)d_in[9];
    const float* w1   = (const float*)d_in[10];
    const float* b1   = (const float*)d_in[11];
    const float* w2   = (const float*)d_in[12];
    const float* b2   = (const float*)d_in[13];
    float* out = (float*)d_out;

    float *ln, *qkv, *ctx, *x2, *ffh, *wqkvr, *wor, *w1r, *w2r;
    cudaGetSymbolAddress((void**)&ln,    g_ln);
    cudaGetSymbolAddress((void**)&qkv,   g_qkv);
    cudaGetSymbolAddress((void**)&ctx,   g_ctx);
    cudaGetSymbolAddress((void**)&x2,    g_x2);
    cudaGetSymbolAddress((void**)&ffh,   g_ffh);
    cudaGetSymbolAddress((void**)&wqkvr, g_wqkv);
    cudaGetSymbolAddress((void**)&wor,   g_wo);
    cudaGetSymbolAddress((void**)&w1r,   g_w1);
    cudaGetSymbolAddress((void**)&w2r,   g_w2);

    cudaFuncSetAttribute(attn_mma, cudaFuncAttributeMaxDynamicSharedMemorySize, ATTN_SMEM);
    cudaFuncSetAttribute(mmagemm<0>, cudaFuncAttributeMaxDynamicSharedMemorySize, GEMM_SMEM);
    cudaFuncSetAttribute(mmagemm<1>, cudaFuncAttributeMaxDynamicSharedMemorySize, GEMM_SMEM);
    cudaFuncSetAttribute(mmagemm<2>, cudaFuncAttributeMaxDynamicSharedMemorySize, GEMM_SMEM);

    pack_qkv<<<2304, 256>>>(wq, wk, wv, wqkvr);
    round_copy<<<576,  256>>>(wo, wor, EMB_ * EMB_);
    round_copy<<<2304, 256>>>(w1, w1r, EMB_ * FF_);
    round_copy<<<2304, 256>>>(w2, w2r, FF_ * EMB_);

    // 1) ln1
    ln_k<<<TOK, 256>>>(x, ln1s, ln1b, ln);
    // 2) fused QKV projection
    mmagemm<0><<<dim3(18, 32), 256, GEMM_SMEM>>>(ln, wqkvr, nullptr, nullptr,
                                                 qkv, EMB_, LDQKV, LDQKV, 24);
    // 3) causal attention
    attn_mma<<<dim3(SEQ_ / 128, 4 * HEADS_), 256, ATTN_SMEM>>>(
        qkv + 0, qkv + 768, qkv + 1536, ctx);
    // 4) output projection + bias + residual
    mmagemm<1><<<dim3(6, 32), 256, GEMM_SMEM>>>(ctx, wor, bo, x, x2,
                                                EMB_, EMB_, EMB_, 24);
    // 5) ln2
    ln_k<<<TOK, 256>>>(x2, ln2s, ln2b, ln);
    // 6) FF1 + bias + GELU
    mmagemm<2><<<dim3(24, 32), 256, GEMM_SMEM>>>(ln, w1r, b1, nullptr, ffh,
                                                 EMB_, FF_, FF_, 24);
    // 7) FF2 + bias + residual -> out
    mmagemm<1><<<dim3(6, 32), 256, GEMM_SMEM>>>(ffh, w2r, b2, x2, out,
                                                FF_, EMB_, EMB_, 96);
}

// round 6
// speedup vs baseline: 1.1341x; 1.1341x over previous
#include <cuda_runtime.h>
#include <cstdint>
#include <math.h>

#define TOK   8192
#define EMB_  768
#define FF_   3072
#define HEADS_ 12
#define SEQ_  2048
#define LDQKV 2304

// ---------------- scratch (device globals; no allocation allowed) ----------
__device__ float g_ln  [TOK * EMB_];
__device__ float g_qkv [TOK * LDQKV];
__device__ float g_ctx [TOK * EMB_];
__device__ float g_x2  [TOK * EMB_];
__device__ float g_ffh [(size_t)TOK * FF_];
__device__ float g_wqkv[EMB_ * LDQKV];
__device__ float g_wo  [EMB_ * EMB_];
__device__ float g_w1  [EMB_ * FF_];
__device__ float g_w2  [FF_ * EMB_];

// ---------------- helpers ---------------------------------------------------
__device__ __forceinline__ uint32_t s2u(const void* p) {
    uint32_t a;
    asm("{ .reg .u64 t; cvta.to.shared.u64 t, %1; cvt.u32.u64 %0, t; }" : "=r"(a) : "l"(p));
    return a;
}
__device__ __forceinline__ float tf32r(float x) {
    uint32_t u; asm("cvt.rna.tf32.f32 %0, %1;" : "=r"(u) : "f"(x));
    return __uint_as_float(u);
}
__device__ __forceinline__ float gelu_f(float x) {
    const float c = 0.79788456080286535588f;
    float t = tanhf(c * (x + 0.044715f * x * x * x));
    return 0.5f * x * (1.f + t);
}
__device__ __forceinline__ void mma8(float c[4], const uint32_t a[4],
                                     uint32_t b0, uint32_t b1) {
    asm volatile("mma.sync.aligned.m16n8k8.row.col.f32.tf32.tf32.f32 "
        "{%0,%1,%2,%3}, {%4,%5,%6,%7}, {%8,%9}, {%0,%1,%2,%3};"
        : "+f"(c[0]), "+f"(c[1]), "+f"(c[2]), "+f"(c[3])
        : "r"(a[0]), "r"(a[1]), "r"(a[2]), "r"(a[3]), "r"(b0), "r"(b1));
}

#define CPA16(d, s) \
    asm volatile("cp.async.cg.shared.global [%0], [%1], 16;" :: "r"(d), "l"(s))
#define CPA_COMMIT() asm volatile("cp.async.commit_group;" ::: "memory")
#define CPA_WAIT2()  asm volatile("cp.async.wait_group 2;" ::: "memory")

// ---------------- weight prep -----------------------------------------------
__global__ __launch_bounds__(256) void round_copy(const float* __restrict__ s,
                                                  float* __restrict__ d, int n)
{
    int i = (blockIdx.x * 256 + threadIdx.x) * 4;
    if (i < n) {
        float4 v = *(const float4*)(s + i);
        v.x = tf32r(v.x); v.y = tf32r(v.y); v.z = tf32r(v.z); v.w = tf32r(v.w);
        *(float4*)(d + i) = v;
    }
}
__global__ __launch_bounds__(256) void pack_qkv(const float* __restrict__ wq,
                                                const float* __restrict__ wk,
                                                const float* __restrict__ wv,
                                                float* __restrict__ d)
{
    int i = blockIdx.x * 256 + threadIdx.x;
    int k = i / EMB_, n = i % EMB_;
    d[(size_t)k * LDQKV + n        ] = tf32r(wq[i]);
    d[(size_t)k * LDQKV + n + 768  ] = tf32r(wk[i]);
    d[(size_t)k * LDQKV + n + 1536 ] = tf32r(wv[i]);
}

// ---------------- layernorm --------------------------------------------------
__global__ __launch_bounds__(256) void ln_k(const float* __restrict__ x,
                                            const float* __restrict__ sc,
                                            const float* __restrict__ sh,
                                            float* __restrict__ out)
{
    int row = blockIdx.x;
    const float* xr = x + (size_t)row * EMB_;
    int t = threadIdx.x;
    float v0 = xr[t], v1 = xr[t + 256], v2 = xr[t + 512];

    __shared__ float red[8];
    float s = v0 + v1 + v2;
    #pragma unroll
    for (int o = 16; o; o >>= 1) s += __shfl_xor_sync(0xffffffffu, s, o);
    if ((t & 31) == 0) red[t >> 5] = s;
    __syncthreads();
    float mean = 0.f;
    #pragma unroll
    for (int i = 0; i < 8; i++) mean += red[i];
    mean *= (1.f / 768.f);

    float d0 = v0 - mean, d1 = v1 - mean, d2 = v2 - mean;
    float vs = d0 * d0 + d1 * d1 + d2 * d2;
    #pragma unroll
    for (int o = 16; o; o >>= 1) vs += __shfl_xor_sync(0xffffffffu, vs, o);
    __syncthreads();
    if ((t & 31) == 0) red[t >> 5] = vs;
    __syncthreads();
    float var = 0.f;
    #pragma unroll
    for (int i = 0; i < 8; i++) var += red[i];
    var *= (1.f / 768.f);
    float rstd = rsqrtf(var + 1e-5f);

    float* orow = out + (size_t)row * EMB_;
    orow[t      ] = tf32r(d0 * rstd * sc[t      ] + sh[t      ]);
    orow[t + 256] = tf32r(d1 * rstd * sc[t + 256] + sh[t + 256]);
    orow[t + 512] = tf32r(d2 * rstd * sc[t + 512] + sh[t + 512]);
}

// ---------------- tf32 mma.sync GEMM: C[M,N] = A[M,K] @ B[K,N] -------------
// CTA 128x128, 256 threads = 8 warps (2x4), warp tile 64x32, 3-stage cp.async.
// __launch_bounds__(256,2): cap 128 regs -> 2 CTAs/SM (smem 107.5KB x2 fits).
#define APITCH 36
#define BPITCH 136
#define A_FLOATS (128 * APITCH)
#define STAGE_FLOATS (A_FLOATS + 32 * BPITCH)
#define NSTG 3
#define GEMM_SMEM (NSTG * STAGE_FLOATS * 4)     // 107520 B

template<int EPI>   // 0 plain; 1 +bias+res; 2 +bias, gelu, tf32-round
__global__ __launch_bounds__(256, 2) void mmagemm(const float* __restrict__ A,
                                                  const float* __restrict__ B,
                                                  const float* __restrict__ bias,
                                                  const float* __restrict__ res,
                                                  float* __restrict__ C,
                                                  int Kd, int N, int ldc, int KT)
{
    extern __shared__ __align__(16) float smf[];
    int tid = threadIdx.x, lane = tid & 31, w = tid >> 5;
    int wm = w >> 2, wn = w & 3;
    int bm = blockIdx.y, bn = blockIdx.x;
    int gr = lane >> 2, t4 = lane & 3;

    float acc[4][4][4];
    #pragma unroll
    for (int i = 0; i < 4; i++)
        #pragma unroll
        for (int j = 0; j < 4; j++)
            #pragma unroll
            for (int e = 0; e < 4; e++) acc[i][j][e] = 0.f;

    auto issue = [&](int kt) {
        float* st = smf + (kt % NSTG) * STAGE_FLOATS;
        int k0 = kt * 32;
        #pragma unroll
        for (int i = 0; i < 4; i++) {
            int chunk = tid + i * 256;
            int row = chunk >> 3, kq = chunk & 7;
            CPA16(s2u(st + row * APITCH + kq * 4),
                  A + (size_t)(bm * 128 + row) * Kd + k0 + kq * 4);
        }
        #pragma unroll
        for (int i = 0; i < 4; i++) {
            int chunk = tid + i * 256;
            int kr = chunk >> 5, nq = chunk & 31;
            CPA16(s2u(st + A_FLOATS + kr * BPITCH + nq * 4),
                  B + (size_t)(k0 + kr) * N + bn * 128 + nq * 4);
        }
    };

    issue(0); CPA_COMMIT();
    issue(1); CPA_COMMIT();

    for (int kt = 0; kt < KT; kt++) {
        if (kt + 2 < KT) issue(kt + 2);
        CPA_COMMIT();
        CPA_WAIT2();
        __syncthreads();

        const float* st = smf + (kt % NSTG) * STAGE_FLOATS;
        const uint32_t* As = (const uint32_t*)st;
        const uint32_t* Bs = (const uint32_t*)(st + A_FLOATS);

        #pragma unroll
        for (int kc = 0; kc < 4; kc++) {
            int kb = kc * 8;
            uint32_t a[4][4];
            #pragma unroll
            for (int mt = 0; mt < 4; mt++) {
                int r = wm * 64 + mt * 16 + gr;
                a[mt][0] = As[(r    ) * APITCH + kb + t4    ];
                a[mt][1] = As[(r + 8) * APITCH + kb + t4    ];
                a[mt][2] = As[(r    ) * APITCH + kb + t4 + 4];
                a[mt][3] = As[(r + 8) * APITCH + kb + t4 + 4];
            }
            uint32_t b[4][2];
            #pragma unroll
            for (int nt = 0; nt < 4; nt++) {
                int n = wn * 32 + nt * 8 + gr;
                b[nt][0] = Bs[(kb + t4    ) * BPITCH + n];
                b[nt][1] = Bs[(kb + t4 + 4) * BPITCH + n];
            }
            #pragma unroll
            for (int mt = 0; mt < 4; mt++)
                #pragma unroll
                for (int nt = 0; nt < 4; nt++)
                    mma8(acc[mt][nt], a[mt], b[nt][0], b[nt][1]);
        }
        __syncthreads();
    }

    float bv[4][2];
    if (EPI >= 1) {
        #pragma unroll
        for (int nt = 0; nt < 4; nt++) {
            int col = bn * 128 + wn * 32 + nt * 8 + t4 * 2;
            bv[nt][0] = bias[col]; bv[nt][1] = bias[col + 1];
        }
    }
    #pragma unroll
    for (int mt = 0; mt < 4; mt++) {
        #pragma unroll
        for (int rr = 0; rr < 2; rr++) {
            int row = bm * 128 + wm * 64 + mt * 16 + gr + rr * 8;
            size_t off = (size_t)row * ldc + bn * 128 + wn * 32 + t4 * 2;
            #pragma unroll
            for (int nt = 0; nt < 4; nt++) {
                float v0 = acc[mt][nt][rr * 2 + 0];
                float v1 = acc[mt][nt][rr * 2 + 1];
                if (EPI >= 1) { v0 += bv[nt][0]; v1 += bv[nt][1]; }
                if (EPI == 2) { v0 = tf32r(gelu_f(v0)); v1 = tf32r(gelu_f(v1)); }
                if (EPI == 1) {
                    float2 r2 = *(const float2*)&res[off + nt * 8];
                    v0 += r2.x; v1 += r2.y;
                }
                *(float2*)&C[off + nt * 8] = make_float2(v0, v1);
            }
        }
    }
}

// ---------------- causal flash attention, tf32 mma.sync --------------------
#define AP 68
#define ATTN_SMEM ((64 + 64 + 128) * AP * 4)   // 69632 B

__global__ __launch_bounds__(256) void attn_mma(const float* __restrict__ Q,
                                                const float* __restrict__ K,
                                                const float* __restrict__ V,
                                                float* __restrict__ O)
{
    extern __shared__ __align__(16) float sm[];
    float* Ks = sm;
    float* Vt = sm + 64 * AP;
    float* Ps = sm + 128 * AP;
    const uint32_t* Ku = (const uint32_t*)Ks;
    const uint32_t* Vu = (const uint32_t*)Vt;
    const uint32_t* Pu = (const uint32_t*)Ps;

    int tid = threadIdx.x, lane = tid & 31, w = tid >> 5;
    int gr = lane >> 2, t4 = lane & 3;
    int bh = blockIdx.y, bb = bh / HEADS_, h = bh % HEADS_;
    int q0 = blockIdx.x * 128;
    size_t baseq = (size_t)bb * SEQ_ * LDQKV + (size_t)h * 64;
    size_t baseo = (size_t)bb * SEQ_ * EMB_  + (size_t)h * 64;
    int r = w * 16 + gr;

    for (int i = tid; i < 128 * 64; i += 256) {
        int rr = i >> 6, dd = i & 63;
        Ps[rr * AP + dd] = tf32r(Q[baseq + (size_t)(q0 + rr) * LDQKV + dd] * 0.125f);
    }
    __syncthreads();
    uint32_t qf[8][4];
    #pragma unroll
    for (int kc = 0; kc < 8; kc++) {
        int kb = kc * 8;
        qf[kc][0] = Pu[(r    ) * AP + kb + t4    ];
        qf[kc][1] = Pu[(r + 8) * AP + kb + t4    ];
        qf[kc][2] = Pu[(r    ) * AP + kb + t4 + 4];
        qf[kc][3] = Pu[(r + 8) * AP + kb + t4 + 4];
    }

    float m0 = -1e30f, m1 = -1e30f, l0 = 0.f, l1 = 0.f;
    float o[8][4];
    #pragma unroll
    for (int nt = 0; nt < 8; nt++)
        #pragma unroll
        for (int e = 0; e < 4; e++) o[nt][e] = 0.f;

    int jmaxt = 2 * blockIdx.x + 1;
    int qlo = q0 + r;

    for (int j = 0; j <= jmaxt; j++) {
        __syncthreads();
        for (int i = tid; i < 64 * 64; i += 256) {
            int rr = i >> 6, dd = i & 63;
            size_t g = baseq + (size_t)(j * 64 + rr) * LDQKV + dd;
            Ks[rr * AP + dd] = tf32r(K[g]);
            Vt[dd * AP + rr] = tf32r(V[g]);
        }
        __syncthreads();

        float s[8][4];
        #pragma unroll
        for (int nt = 0; nt < 8; nt++)
            #pragma unroll
            for (int e = 0; e < 4; e++) s[nt][e] = 0.f;
        #pragma unroll
        for (int kc = 0; kc < 8; kc++) {
            int kb = kc * 8;
            #pragma unroll
            for (int nt = 0; nt < 8; nt++) {
                uint32_t b0 = Ku[(nt * 8 + gr) * AP + kb + t4    ];
                uint32_t b1 = Ku[(nt * 8 + gr) * AP + kb + t4 + 4];
                mma8(s[nt], qf[kc], b0, b1);
            }
        }

        if (j * 64 + 63 > q0 + w * 16) {
            #pragma unroll
            for (int nt = 0; nt < 8; nt++) {
                int c0 = j * 64 + nt * 8 + 2 * t4;
                if (c0     > qlo    ) s[nt][0] = -1e30f;
                if (c0 + 1 > qlo    ) s[nt][1] = -1e30f;
                if (c0     > qlo + 8) s[nt][2] = -1e30f;
                if (c0 + 1 > qlo + 8) s[nt][3] = -1e30f;
            }
        }

        float mt0 = -1e30f, mt1 = -1e30f;
        #pragma unroll
        for (int nt = 0; nt < 8; nt++) {
            mt0 = fmaxf(mt0, fmaxf(s[nt][0], s[nt][1]));
            mt1 = fmaxf(mt1, fmaxf(s[nt][2], s[nt][3]));
        }
        mt0 = fmaxf(mt0, __shfl_xor_sync(0xffffffffu, mt0, 1));
        mt0 = fmaxf(mt0, __shfl_xor_sync(0xffffffffu, mt0, 2));
        mt1 = fmaxf(mt1, __shfl_xor_sync(0xffffffffu, mt1, 1));
        mt1 = fmaxf(mt1, __shfl_xor_sync(0xffffffffu, mt1, 2));
        float mn0 = fmaxf(m0, mt0), mn1 = fmaxf(m1, mt1);
        float a0 = __expf(m0 - mn0), a1 = __expf(m1 - mn1);
        float ps0 = 0.f, ps1 = 0.f;
        #pragma unroll
        for (int nt = 0; nt < 8; nt++) {
            s[nt][0] = __expf(s[nt][0] - mn0); ps0 += s[nt][0];
            s[nt][1] = __expf(s[nt][1] - mn0); ps0 += s[nt][1];
            s[nt][2] = __expf(s[nt][2] - mn1); ps1 += s[nt][2];
            s[nt][3] = __expf(s[nt][3] - mn1); ps1 += s[nt][3];
        }
        ps0 += __shfl_xor_sync(0xffffffffu, ps0, 1);
        ps0 += __shfl_xor_sync(0xffffffffu, ps0, 2);
        ps1 += __shfl_xor_sync(0xffffffffu, ps1, 1);
        ps1 += __shfl_xor_sync(0xffffffffu, ps1, 2);
        l0 = l0 * a0 + ps0; l1 = l1 * a1 + ps1;
        m0 = mn0; m1 = mn1;
        #pragma unroll
        for (int nt = 0; nt < 8; nt++) {
            o[nt][0] *= a0; o[nt][1] *= a0; o[nt][2] *= a1; o[nt][3] *= a1;
        }

        #pragma unroll
        for (int nt = 0; nt < 8; nt++) {
            int cc = nt * 8 + 2 * t4;
            *(float2*)&Ps[(r    ) * AP + cc] = make_float2(tf32r(s[nt][0]), tf32r(s[nt][1]));
            *(float2*)&Ps[(r + 8) * AP + cc] = make_float2(tf32r(s[nt][2]), tf32r(s[nt][3]));
        }
        __syncwarp();

        #pragma unroll
        for (int kc = 0; kc < 8; kc++) {
            int kb = kc * 8;
            uint32_t pa[4];
            pa[0] = Pu[(r    ) * AP + kb + t4    ];
            pa[1] = Pu[(r + 8) * AP + kb + t4    ];
            pa[2] = Pu[(r    ) * AP + kb + t4 + 4];
            pa[3] = Pu[(r + 8) * AP + kb + t4 + 4];
            #pragma unroll
            for (int nt = 0; nt < 8; nt++) {
                uint32_t b0 = Vu[(nt * 8 + gr) * AP + kb + t4    ];
                uint32_t b1 = Vu[(nt * 8 + gr) * AP + kb + t4 + 4];
                mma8(o[nt], pa, b0, b1);
            }
        }
    }

    float inv0 = 1.f / l0, inv1 = 1.f / l1;
    size_t off0 = baseo + (size_t)(q0 + r    ) * EMB_;
    size_t off1 = baseo + (size_t)(q0 + r + 8) * EMB_;
    #pragma unroll
    for (int nt = 0; nt < 8; nt++) {
        int cc = nt * 8 + 2 * t4;
        *(float2*)&O[off0 + cc] = make_float2(tf32r(o[nt][0] * inv0), tf32r(o[nt][1] * inv0));
        *(float2*)&O[off1 + cc] = make_float2(tf32r(o[nt][2] * inv1), tf32r(o[nt][3] * inv1));
    }
}

// ---------------- launch ---------------------------------------------------
extern "C" void kernel_launch(void* const* d_in, const int* in_sizes, int n_in,
                              void* d_out, int out_size)
{
    const float* x    = (const float*)d_in[0];
    const float* ln1s = (const float*)d_in[1];
    const float* ln1b = (const float*)d_in[2];
    const float* wq   = (const float*)d_in[3];
    const float* wk   = (const float*)d_in[4];
    const float* wv   = (const float*)d_in[5];
    const float* wo   = (const float*)d_in[6];
    const float* bo   = (const float*)d_in[7];
    const float* ln2s = (const float*)d_in[8];
    const float* ln2b = (const float*)d_in[9];
    const float* w1   = (const float*)d_in[10];
    const float* b1   = (const float*)d_in[11];
    const float* w2   = (const float*)d_in[12];
    const float* b2   = (const float*)d_in[13];
    float* out = (float*)d_out;

    float *ln, *qkv, *ctx, *x2, *ffh, *wqkvr, *wor, *w1r, *w2r;
    cudaGetSymbolAddress((void**)&ln,    g_ln);
    cudaGetSymbolAddress((void**)&qkv,   g_qkv);
    cudaGetSymbolAddress((void**)&ctx,   g_ctx);
    cudaGetSymbolAddress((void**)&x2,    g_x2);
    cudaGetSymbolAddress((void**)&ffh,   g_ffh);
    cudaGetSymbolAddress((void**)&wqkvr, g_wqkv);
    cudaGetSymbolAddress((void**)&wor,   g_wo);
    cudaGetSymbolAddress((void**)&w1r,   g_w1);
    cudaGetSymbolAddress((void**)&w2r,   g_w2);

    cudaFuncSetAttribute(attn_mma, cudaFuncAttributeMaxDynamicSharedMemorySize, ATTN_SMEM);
    cudaFuncSetAttribute(mmagemm<0>, cudaFuncAttributeMaxDynamicSharedMemorySize, GEMM_SMEM);
    cudaFuncSetAttribute(mmagemm<1>, cudaFuncAttributeMaxDynamicSharedMemorySize, GEMM_SMEM);
    cudaFuncSetAttribute(mmagemm<2>, cudaFuncAttributeMaxDynamicSharedMemorySize, GEMM_SMEM);

    pack_qkv<<<2304, 256>>>(wq, wk, wv, wqkvr);
    round_copy<<<576,  256>>>(wo, wor, EMB_ * EMB_);
    round_copy<<<2304, 256>>>(w1, w1r, EMB_ * FF_);
    round_copy<<<2304, 256>>>(w2, w2r, FF_ * EMB_);

    // 1) ln1
    ln_k<<<TOK, 256>>>(x, ln1s, ln1b, ln);
    // 2) fused QKV projection
    mmagemm<0><<<dim3(18, 64), 256, GEMM_SMEM>>>(ln, wqkvr, nullptr, nullptr,
                                                 qkv, EMB_, LDQKV, LDQKV, 24);
    // 3) causal attention
    attn_mma<<<dim3(SEQ_ / 128, 4 * HEADS_), 256, ATTN_SMEM>>>(
        qkv + 0, qkv + 768, qkv + 1536, ctx);
    // 4) output projection + bias + residual
    mmagemm<1><<<dim3(6, 64), 256, GEMM_SMEM>>>(ctx, wor, bo, x, x2,
                                                EMB_, EMB_, EMB_, 24);
    // 5) ln2
    ln_k<<<TOK, 256>>>(x2, ln2s, ln2b, ln);
    // 6) FF1 + bias + GELU
    mmagemm<2><<<dim3(24, 64), 256, GEMM_SMEM>>>(ln, w1r, b1, nullptr, ffh,
                                                 EMB_, FF_, FF_, 24);
    // 7) FF2 + bias + residual -> out
    mmagemm<1><<<dim3(6, 64), 256, GEMM_SMEM>>>(ffh, w2r, b2, x2, out,
                                                FF_, EMB_, EMB_, 96);
}